// round 15
// baseline (speedup 1.0000x reference)
#include <cuda_runtime.h>
#include <cstdint>

// FINAL — R5 configuration. Best measured: wall 121.92us (runs: 122.27/122.56/
// 122.14/121.92), kernel ~115.8us, rel_err 0.0, DRAM pipe 83.4-84.1% = the
// GB300 mixed read+write HBM ceiling (~6.6 TB/s) for this 822 MB stream.
//
// x: (131072, 28, 28) fp32. rows = 4 int32, cols = 4 int32.
// out[i,h,w] = mute(x) if (h in rows) || (w in cols) else x
//   mute(x): frexp e>1  =>  replace exponent field with 126 (|x|>=2 -> [0.5,1)),
//   exact bit manipulation, idempotent => row-then-col ordering collapses to a
//   single mask test per element.
// Mask depends only on float4_index % 196 -> per-block 196-entry smem LUT;
// phase tracked incrementally (step 256 mod 196 == 60), no per-iter mod chain.
// UNROLL=4 front-batched LDG.128s (MLP=4), 256 threads, 27 regs, occ ~84%.
//
// Falsified alternatives (all benchmarked this session):
//   UNROLL=8 (regs 40, occ 63%, cross-CTA L1tex-queue spread regression)
//   persistent one-wave grid (-11%: per-warp MLP serialized across chunks)
//   512-thread blocks (tied), 256-bit v8 ld/st (tied — DRAM cap path-indep)
//   __ldcs+__stcs, __ldcg, __stcs-only cache hints (each 0.5-1% negative)

static constexpr int HW4 = 196;                     // float4 positions per image
static constexpr long long NELEM = 131072LL * 784;  // 102,760,448
static constexpr int N4 = (int)(NELEM / 4);         // 25,690,112 = 25088 * 1024
static constexpr int UNROLL = 4;
static constexpr int THREADS = 256;
static constexpr int STEP = 256 % HW4;              // 60

__device__ __forceinline__ float mute1(float x) {
    unsigned b  = __float_as_uint(x);
    unsigned ef = b & 0x7F800000u;                   // exponent field in place
    unsigned b2 = (b & 0x807FFFFFu) | 0x3F000000u;   // exponent -> 126
    // biased exp in [128,254]  <=>  ef in [0x40000000, 0x7F800000)
    // (excludes inf/nan at 255; subnormals/zero have ef < threshold)
    return __uint_as_float((ef - 0x40000000u < 0x3F800000u) ? b2 : b);
}

__global__ void __launch_bounds__(THREADS) mute_kernel(
    const float4* __restrict__ x,
    const int* __restrict__ rows,
    const int* __restrict__ cols,
    float4* __restrict__ out)
{
    __shared__ unsigned char lut[HW4];

    int tid = threadIdx.x;
    if (tid < HW4) {
        int p = tid * 4;          // element offset within 28x28 image
        int h = p / 28;
        int w = p - h * 28;       // float4 never crosses a row (4 | 28)
        int r0 = rows[0], r1 = rows[1], r2 = rows[2], r3 = rows[3];
        int c0 = cols[0], c1 = cols[1], c2 = cols[2], c3 = cols[3];
        bool rm = (h == r0) | (h == r1) | (h == r2) | (h == r3);
        unsigned m = 0;
        #pragma unroll
        for (int k = 0; k < 4; k++) {
            bool cm = (w + k == c0) | (w + k == c1) | (w + k == c2) | (w + k == c3);
            if (rm | cm) m |= (1u << k);
        }
        lut[tid] = (unsigned char)m;
    }
    __syncthreads();

    int base = blockIdx.x * (THREADS * UNROLL) + tid;

    // Front-batch 4 LDG.128s (MLP=4), default caching
    float4 v[UNROLL];
    #pragma unroll
    for (int k = 0; k < UNROLL; k++) {
        v[k] = x[base + k * THREADS];
    }

    // Incremental phase: (base + k*256) % 196
    int ph = base % HW4;

    #pragma unroll
    for (int k = 0; k < UNROLL; k++) {
        unsigned m = lut[ph];
        v[k].x = (m & 1u) ? mute1(v[k].x) : v[k].x;
        v[k].y = (m & 2u) ? mute1(v[k].y) : v[k].y;
        v[k].z = (m & 4u) ? mute1(v[k].z) : v[k].z;
        v[k].w = (m & 8u) ? mute1(v[k].w) : v[k].w;
        out[base + k * THREADS] = v[k];
        ph += STEP;
        if (ph >= HW4) ph -= HW4;
    }
}

extern "C" void kernel_launch(void* const* d_in, const int* in_sizes, int n_in,
                              void* d_out, int out_size) {
    const float4* x = (const float4*)d_in[0];
    const int* rows = (const int*)d_in[1];
    const int* cols = (const int*)d_in[2];
    float4* out     = (float4*)d_out;

    const int blocks = N4 / (THREADS * UNROLL);  // 25,088 exact
    mute_kernel<<<blocks, THREADS>>>(x, rows, cols, out);
}

// round 16
// speedup vs baseline: 1.0026x; 1.0026x over previous
#include <cuda_runtime.h>
#include <cstdint>

// FINAL — R5 configuration (converged). Six identical-config runs measured
// 121.92–123.04us wall (best 121.92), kernel 115.6–116.8us, rel_err 0.0 every
// run, DRAM pipe 82.9–84.1% = the GB300 mixed read+write HBM ceiling
// (~6.6 TB/s) for this 822 MB once-touched stream.
//
// x: (131072, 28, 28) fp32. rows = 4 int32, cols = 4 int32.
// out[i,h,w] = mute(x) if (h in rows) || (w in cols) else x
//   mute(x): frexp e>1  =>  replace exponent field with 126 (|x|>=2 -> [0.5,1)),
//   exact bit manipulation, idempotent => the reference's row-pass-then-col-pass
//   collapses to a single mask test per element.
// Mask depends only on float4_index % 196 -> per-block 196-entry smem LUT;
// phase tracked incrementally (step 256 mod 196 == 60), no per-iter mod chain.
// UNROLL=4 front-batched LDG.128s (MLP=4), 256 threads, 27 regs, occ ~84%.
//
// Falsified alternatives (all benchmarked this session):
//   UNROLL=8 (regs 40, occ 63%, cross-CTA L1tex-queue spread regression)
//   persistent one-wave grid (-11%: per-warp MLP serialized across chunks)
//   512-thread blocks (tied), 256-bit v8 ld/st (tied — DRAM cap path-indep)
//   __ldcs+__stcs, __ldcg, __stcs-only cache hints (all within/below noise)

static constexpr int HW4 = 196;                     // float4 positions per image
static constexpr long long NELEM = 131072LL * 784;  // 102,760,448
static constexpr int N4 = (int)(NELEM / 4);         // 25,690,112 = 25088 * 1024
static constexpr int UNROLL = 4;
static constexpr int THREADS = 256;
static constexpr int STEP = 256 % HW4;              // 60

__device__ __forceinline__ float mute1(float x) {
    unsigned b  = __float_as_uint(x);
    unsigned ef = b & 0x7F800000u;                   // exponent field in place
    unsigned b2 = (b & 0x807FFFFFu) | 0x3F000000u;   // exponent -> 126
    // biased exp in [128,254]  <=>  ef in [0x40000000, 0x7F800000)
    // (excludes inf/nan at 255; subnormals/zero have ef < threshold)
    return __uint_as_float((ef - 0x40000000u < 0x3F800000u) ? b2 : b);
}

__global__ void __launch_bounds__(THREADS) mute_kernel(
    const float4* __restrict__ x,
    const int* __restrict__ rows,
    const int* __restrict__ cols,
    float4* __restrict__ out)
{
    __shared__ unsigned char lut[HW4];

    int tid = threadIdx.x;
    if (tid < HW4) {
        int p = tid * 4;          // element offset within 28x28 image
        int h = p / 28;
        int w = p - h * 28;       // float4 never crosses a row (4 | 28)
        int r0 = rows[0], r1 = rows[1], r2 = rows[2], r3 = rows[3];
        int c0 = cols[0], c1 = cols[1], c2 = cols[2], c3 = cols[3];
        bool rm = (h == r0) | (h == r1) | (h == r2) | (h == r3);
        unsigned m = 0;
        #pragma unroll
        for (int k = 0; k < 4; k++) {
            bool cm = (w + k == c0) | (w + k == c1) | (w + k == c2) | (w + k == c3);
            if (rm | cm) m |= (1u << k);
        }
        lut[tid] = (unsigned char)m;
    }
    __syncthreads();

    int base = blockIdx.x * (THREADS * UNROLL) + tid;

    // Front-batch 4 LDG.128s (MLP=4), default caching
    float4 v[UNROLL];
    #pragma unroll
    for (int k = 0; k < UNROLL; k++) {
        v[k] = x[base + k * THREADS];
    }

    // Incremental phase: (base + k*256) % 196
    int ph = base % HW4;

    #pragma unroll
    for (int k = 0; k < UNROLL; k++) {
        unsigned m = lut[ph];
        v[k].x = (m & 1u) ? mute1(v[k].x) : v[k].x;
        v[k].y = (m & 2u) ? mute1(v[k].y) : v[k].y;
        v[k].z = (m & 4u) ? mute1(v[k].z) : v[k].z;
        v[k].w = (m & 8u) ? mute1(v[k].w) : v[k].w;
        out[base + k * THREADS] = v[k];
        ph += STEP;
        if (ph >= HW4) ph -= HW4;
    }
}

extern "C" void kernel_launch(void* const* d_in, const int* in_sizes, int n_in,
                              void* d_out, int out_size) {
    const float4* x = (const float4*)d_in[0];
    const int* rows = (const int*)d_in[1];
    const int* cols = (const int*)d_in[2];
    float4* out     = (float4*)d_out;

    const int blocks = N4 / (THREADS * UNROLL);  // 25,088 exact
    mute_kernel<<<blocks, THREADS>>>(x, rows, cols, out);
}

// round 17
// speedup vs baseline: 1.0108x; 1.0081x over previous
#include <cuda_runtime.h>
#include <cstdint>

// R5 config + prologue reorder: issue the 4 independent LDG.128s BEFORE the
// LUT build + __syncthreads(), hiding the per-CTA prologue (rows/cols load,
// integer work, barrier) under the ~600-cycle DRAM latency of the first loads.
// Steady-state code identical to the converged best (121.92us wall).
//
// x: (131072, 28, 28) fp32. rows = 4 int32, cols = 4 int32.
// out[i,h,w] = mute(x) if (h in rows) || (w in cols) else x
//   mute(x): frexp e>1 => exponent field -> 126; exact bit op, idempotent =>
//   row-pass-then-col-pass collapses to a single mask test.
// Mask = f(float4_index % 196) via per-block smem LUT; incremental phase
// (step 256 mod 196 == 60). UNROLL=4, 256 threads, MLP=4.

static constexpr int HW4 = 196;                     // float4 positions per image
static constexpr long long NELEM = 131072LL * 784;  // 102,760,448
static constexpr int N4 = (int)(NELEM / 4);         // 25,690,112 = 25088 * 1024
static constexpr int UNROLL = 4;
static constexpr int THREADS = 256;
static constexpr int STEP = 256 % HW4;              // 60

__device__ __forceinline__ float mute1(float x) {
    unsigned b  = __float_as_uint(x);
    unsigned ef = b & 0x7F800000u;                   // exponent field in place
    unsigned b2 = (b & 0x807FFFFFu) | 0x3F000000u;   // exponent -> 126
    // biased exp in [128,254]  <=>  ef in [0x40000000, 0x7F800000)
    // (excludes inf/nan at 255; subnormals/zero have ef < threshold)
    return __uint_as_float((ef - 0x40000000u < 0x3F800000u) ? b2 : b);
}

__global__ void __launch_bounds__(THREADS) mute_kernel(
    const float4* __restrict__ x,
    const int* __restrict__ rows,
    const int* __restrict__ cols,
    float4* __restrict__ out)
{
    __shared__ unsigned char lut[HW4];

    int tid = threadIdx.x;
    int base = blockIdx.x * (THREADS * UNROLL) + tid;

    // Issue the 4 LDG.128s FIRST — independent of the LUT; their latency hides
    // the entire prologue below (rows/cols loads, mask math, barrier).
    float4 v[UNROLL];
    #pragma unroll
    for (int k = 0; k < UNROLL; k++) {
        v[k] = x[base + k * THREADS];
    }

    if (tid < HW4) {
        int p = tid * 4;          // element offset within 28x28 image
        int h = p / 28;
        int w = p - h * 28;       // float4 never crosses a row (4 | 28)
        int r0 = rows[0], r1 = rows[1], r2 = rows[2], r3 = rows[3];
        int c0 = cols[0], c1 = cols[1], c2 = cols[2], c3 = cols[3];
        bool rm = (h == r0) | (h == r1) | (h == r2) | (h == r3);
        unsigned m = 0;
        #pragma unroll
        for (int k = 0; k < 4; k++) {
            bool cm = (w + k == c0) | (w + k == c1) | (w + k == c2) | (w + k == c3);
            if (rm | cm) m |= (1u << k);
        }
        lut[tid] = (unsigned char)m;
    }
    __syncthreads();

    // Incremental phase: (base + k*256) % 196
    int ph = base % HW4;

    #pragma unroll
    for (int k = 0; k < UNROLL; k++) {
        unsigned m = lut[ph];
        v[k].x = (m & 1u) ? mute1(v[k].x) : v[k].x;
        v[k].y = (m & 2u) ? mute1(v[k].y) : v[k].y;
        v[k].z = (m & 4u) ? mute1(v[k].z) : v[k].z;
        v[k].w = (m & 8u) ? mute1(v[k].w) : v[k].w;
        out[base + k * THREADS] = v[k];
        ph += STEP;
        if (ph >= HW4) ph -= HW4;
    }
}

extern "C" void kernel_launch(void* const* d_in, const int* in_sizes, int n_in,
                              void* d_out, int out_size) {
    const float4* x = (const float4*)d_in[0];
    const int* rows = (const int*)d_in[1];
    const int* cols = (const int*)d_in[2];
    float4* out     = (float4*)d_out;

    const int blocks = N4 / (THREADS * UNROLL);  // 25,088 exact
    mute_kernel<<<blocks, THREADS>>>(x, rows, cols, out);
}